// round 10
// baseline (speedup 1.0000x reference)
#include <cuda_runtime.h>
#include <cuda_bf16.h>
#include <cstdint>

#define BB    2
#define SEQ   2048
#define DIM   1024
#define HEADS 16
#define DKH   64
#define MTOT  (BB * SEQ * DIM)      // 4M elements
#define NBH   (BB * HEADS)

typedef __nv_bfloat16 bf16;

// Scratch (allocation-free rule: __device__ globals), 16B-aligned for vector IO
__device__ __align__(16) bf16 g_inq_hi[MTOT], g_inq_lo[MTOT];
__device__ __align__(16) bf16 g_ink_hi[MTOT], g_ink_lo[MTOT];
__device__ __align__(16) bf16 g_inv_hi[MTOT], g_inv_lo[MTOT];
__device__ __align__(16) bf16 g_wq_hi[DIM*DIM], g_wq_lo[DIM*DIM];
__device__ __align__(16) bf16 g_wk_hi[DIM*DIM], g_wk_lo[DIM*DIM];
__device__ __align__(16) bf16 g_wv_hi[DIM*DIM], g_wv_lo[DIM*DIM];
__device__ __align__(16) bf16 g_wo_hi[DIM*DIM], g_wo_lo[DIM*DIM];
__device__ __align__(16) bf16 g_q_hi[MTOT],  g_q_lo[MTOT];
__device__ __align__(16) bf16 g_k_hi[MTOT],  g_k_lo[MTOT];
__device__ __align__(16) bf16 g_bl_hi[MTOT], g_bl_lo[MTOT];
__device__ __align__(16) float g_v[MTOT];

// ===========================================================================
// PTX primitives (sm_80-era — assembles under compute_103)
// ===========================================================================
__device__ __forceinline__ uint32_t smem_u32(const void* p) {
    uint32_t a;
    asm("{ .reg .u64 t; cvta.to.shared.u64 t, %1; cvt.u32.u64 %0, t; }"
        : "=r"(a) : "l"(p));
    return a;
}

__device__ __forceinline__ void mma16816(float* c, const uint32_t* a, const uint32_t* b) {
    asm volatile("mma.sync.aligned.m16n8k16.row.col.f32.bf16.bf16.f32 "
        "{%0,%1,%2,%3}, {%4,%5,%6,%7}, {%8,%9}, {%0,%1,%2,%3};"
        : "+f"(c[0]), "+f"(c[1]), "+f"(c[2]), "+f"(c[3])
        : "r"(a[0]), "r"(a[1]), "r"(a[2]), "r"(a[3]), "r"(b[0]), "r"(b[1]));
}

#define STB  80   // bytes per smem tile row (64B data + 16B pad)

__device__ __forceinline__ void ldsmA4(uint32_t* r, uint32_t base, int m0, int k0, int lane) {
    uint32_t addr = base + (uint32_t)(m0 + (lane & 15)) * STB
                         + (uint32_t)(k0 + (lane >> 4) * 8) * 2;
    asm volatile("ldmatrix.sync.aligned.m8n8.x4.shared.b16 {%0,%1,%2,%3}, [%4];"
        : "=r"(r[0]), "=r"(r[1]), "=r"(r[2]), "=r"(r[3]) : "r"(addr));
}

__device__ __forceinline__ void ldsmB2(uint32_t* r, uint32_t base, int n0, int k0, int lane) {
    uint32_t addr = base + (uint32_t)(n0 + (lane & 7)) * STB
                         + (uint32_t)(k0 + ((lane >> 3) & 1) * 8) * 2;
    asm volatile("ldmatrix.sync.aligned.m8n8.x2.shared.b16 {%0,%1}, [%2];"
        : "=r"(r[0]), "=r"(r[1]) : "r"(addr));
}

__device__ __forceinline__ void cp16(uint32_t dst, const void* src) {
    asm volatile("cp.async.ca.shared.global [%0], [%1], 16;"
        :: "r"(dst), "l"(src) : "memory");
}
__device__ __forceinline__ void cp_commit() {
    asm volatile("cp.async.commit_group;" ::: "memory");
}
template<int N> __device__ __forceinline__ void cp_wait() {
    asm volatile("cp.async.wait_group %0;" :: "n"(N) : "memory");
}

// ===========================================================================
// split-bf16 helpers
// ===========================================================================
__device__ __forceinline__ uint32_t pack2(bf16 a, bf16 b) {
    return (uint32_t)__bfloat16_as_ushort(a) | ((uint32_t)__bfloat16_as_ushort(b) << 16);
}
__device__ __forceinline__ void split2(float a, float b, uint32_t& hi, uint32_t& lo) {
    bf16 ha = __float2bfloat16_rn(a);
    bf16 hb = __float2bfloat16_rn(b);
    bf16 la = __float2bfloat16_rn(a - __bfloat162float(ha));
    bf16 lb = __float2bfloat16_rn(b - __bfloat162float(hb));
    hi = pack2(ha, hb);
    lo = pack2(la, lb);
}

// Batched elementwise fp32 -> (hi, lo) bf16 (grid.y selects tensor)
struct SplitBatch {
    const float4* src[4];
    uint2* hi[4];
    uint2* lo[4];
};

__global__ __launch_bounds__(256) void split_batch(SplitBatch args, int n4)
{
    const int z = blockIdx.y;
    int i = blockIdx.x * 256 + threadIdx.x;
    if (i < n4) {
        float4 v = args.src[z][i];
        uint32_t h01, l01, h23, l23;
        split2(v.x, v.y, h01, l01);
        split2(v.z, v.w, h23, l23);
        args.hi[z][i] = make_uint2(h01, h23);
        args.lo[z][i] = make_uint2(l01, l23);
    }
}

// ===========================================================================
// cp.async tile loaders: one K=32 chunk (64B/row), 128 rows, hi+lo
// ===========================================================================
__device__ __forceinline__ void cpa_tile_128(
    const bf16* __restrict__ hi, const bf16* __restrict__ lo, int ld,
    uint32_t smem_hi, uint32_t smem_lo, int tid)
{
#pragma unroll
    for (int it = 0; it < 2; it++) {
        int idx = tid + it * 256;        // 0..511
        int r = idx >> 2, j = idx & 3;
        size_t go = (size_t)r * ld + j * 8;
        uint32_t so = (uint32_t)r * STB + j * 16;
        cp16(smem_hi + so, hi + go);
        cp16(smem_lo + so, lo + go);
    }
}

// Smem offsets within one pipeline buffer (tile = 128 x STB = 10240 B)
#define T_AHI 0u
#define T_ALO 10240u
#define T_BHI 20480u
#define T_BLO 30720u
#define BUFSZ 40960u
#define SMEM_G (2 * 40960)           // double-buffered
#define OFF_BHI_PV 20480u
#define OFF_BLO_PV 25600u
#define SMEM_PV 30720

// ===========================================================================
// 3-term MMA over one 32-K chunk (shared fragments, long RAW distance)
// ===========================================================================
template<int NJ>
__device__ __forceinline__ void mma_chunk(
    float (*acc)[NJ][4], uint32_t aHi, uint32_t aLo, uint32_t bHi, uint32_t bLo,
    int wm, int wn, int lane)
{
#pragma unroll
    for (int k0 = 0; k0 < 32; k0 += 16) {
        uint32_t ah0[4], ah1[4], al0[4], al1[4];
        ldsmA4(ah0, aHi, wm,      k0, lane);
        ldsmA4(ah1, aHi, wm + 16, k0, lane);
        ldsmA4(al0, aLo, wm,      k0, lane);
        ldsmA4(al1, aLo, wm + 16, k0, lane);
        uint32_t bf[NJ][2];
#pragma unroll
        for (int j = 0; j < NJ; j++) ldsmB2(bf[j], bHi, wn + j * 8, k0, lane);
#pragma unroll
        for (int j = 0; j < NJ; j++) {
            mma16816(acc[0][j], ah0, bf[j]);
            mma16816(acc[1][j], ah1, bf[j]);
        }
#pragma unroll
        for (int j = 0; j < NJ; j++) {
            mma16816(acc[0][j], al0, bf[j]);
            mma16816(acc[1][j], al1, bf[j]);
        }
#pragma unroll
        for (int j = 0; j < NJ; j++) ldsmB2(bf[j], bLo, wn + j * 8, k0, lane);
#pragma unroll
        for (int j = 0; j < NJ; j++) {
            mma16816(acc[0][j], ah0, bf[j]);
            mma16816(acc[1][j], ah1, bf[j]);
        }
    }
}

// ===========================================================================
// Merged QKV projection: grid.z selects (input, weight, bias, output).
// z=0 -> Q (split out), z=1 -> K (split out), z=2 -> V (fp32 out).
// ===========================================================================
struct ProjArgs {
    const bf16* Ah[3];
    const bf16* Al[3];
    const bf16* Bh[3];
    const bf16* Bl[3];
    const float* bias[3];
    bf16* Chi[3];
    bf16* Clo[3];
    float* Cf;           // z == 2
};

__global__ __launch_bounds__(256, 2) void gemm_qkv(ProjArgs args)
{
    extern __shared__ char smem[];
    const uint32_t sb = smem_u32(smem);
    const int tid  = threadIdx.x;
    const int wid  = tid >> 5, lane = tid & 31;
    const int z   = blockIdx.z;
    const int bm = blockIdx.y * 128, bn = blockIdx.x * 128;
    const int wm = (wid & 3) * 32;
    const int wn = (wid >> 2) * 64;

    const bf16* Ah = args.Ah[z] + (size_t)bm * DIM;
    const bf16* Al = args.Al[z] + (size_t)bm * DIM;
    const bf16* Bh = args.Bh[z] + (size_t)bn * DIM;
    const bf16* Bl = args.Bl[z] + (size_t)bn * DIM;
    const float* bias = args.bias[z];
    const int nc = DIM >> 5;

    cpa_tile_128(Ah, Al, DIM, sb + T_AHI, sb + T_ALO, tid);
    cpa_tile_128(Bh, Bl, DIM, sb + T_BHI, sb + T_BLO, tid);
    cp_commit();

    float acc[2][8][4] = {};
    for (int c = 0; c < nc; c++) {
        cp_wait<0>();
        __syncthreads();
        if (c + 1 < nc) {
            uint32_t bo = sb + ((c + 1) & 1) * BUFSZ;
            cpa_tile_128(Ah + (c+1)*32, Al + (c+1)*32, DIM, bo + T_AHI, bo + T_ALO, tid);
            cpa_tile_128(Bh + (c+1)*32, Bl + (c+1)*32, DIM, bo + T_BHI, bo + T_BLO, tid);
            cp_commit();
        }
        uint32_t bo = sb + (c & 1) * BUFSZ;
        mma_chunk<8>(acc, bo + T_AHI, bo + T_ALO, bo + T_BHI, bo + T_BLO, wm, wn, lane);
    }

    const int g  = lane >> 2;
    const int tg = (lane & 3) * 2;
#pragma unroll
    for (int i = 0; i < 2; i++) {
#pragma unroll
        for (int j = 0; j < 8; j++) {
            int row = bm + wm + i * 16 + g;
            int col = bn + wn + j * 8 + tg;
            float b0 = bias[col], b1 = bias[col + 1];
            float x0 = acc[i][j][0] + b0, x1 = acc[i][j][1] + b1;
            float x2 = acc[i][j][2] + b0, x3 = acc[i][j][3] + b1;
            if (z == 2) {
                *(float2*)&args.Cf[(size_t)row * DIM + col] = make_float2(x0, x1);
                *(float2*)&args.Cf[(size_t)(row + 8) * DIM + col] = make_float2(x2, x3);
            } else {
                uint32_t h, l;
                split2(x0, x1, h, l);
                *(uint32_t*)&args.Chi[z][(size_t)row * DIM + col] = h;
                *(uint32_t*)&args.Clo[z][(size_t)row * DIM + col] = l;
                split2(x2, x3, h, l);
                *(uint32_t*)&args.Chi[z][(size_t)(row + 8) * DIM + col] = h;
                *(uint32_t*)&args.Clo[z][(size_t)(row + 8) * DIM + col] = l;
            }
        }
    }
}

// ===========================================================================
// Wo projection: C fp32 = A(hi/lo) @ B(hi/lo)^T + bias
// ===========================================================================
__global__ __launch_bounds__(256, 2) void gemm_wo(
    const bf16* __restrict__ Ahi, const bf16* __restrict__ Alo,
    const bf16* __restrict__ Bhi, const bf16* __restrict__ Blo,
    const float* __restrict__ bias, float* __restrict__ Cf)
{
    extern __shared__ char smem[];
    const uint32_t sb = smem_u32(smem);
    const int tid  = threadIdx.x;
    const int wid  = tid >> 5, lane = tid & 31;
    const int bm = blockIdx.y * 128, bn = blockIdx.x * 128;
    const int wm = (wid & 3) * 32;
    const int wn = (wid >> 2) * 64;

    const bf16* Ah = Ahi + (size_t)bm * DIM;
    const bf16* Al = Alo + (size_t)bm * DIM;
    const bf16* Bh = Bhi + (size_t)bn * DIM;
    const bf16* Bl = Blo + (size_t)bn * DIM;
    const int nc = DIM >> 5;

    cpa_tile_128(Ah, Al, DIM, sb + T_AHI, sb + T_ALO, tid);
    cpa_tile_128(Bh, Bl, DIM, sb + T_BHI, sb + T_BLO, tid);
    cp_commit();

    float acc[2][8][4] = {};
    for (int c = 0; c < nc; c++) {
        cp_wait<0>();
        __syncthreads();
        if (c + 1 < nc) {
            uint32_t bo = sb + ((c + 1) & 1) * BUFSZ;
            cpa_tile_128(Ah + (c+1)*32, Al + (c+1)*32, DIM, bo + T_AHI, bo + T_ALO, tid);
            cpa_tile_128(Bh + (c+1)*32, Bl + (c+1)*32, DIM, bo + T_BHI, bo + T_BLO, tid);
            cp_commit();
        }
        uint32_t bo = sb + (c & 1) * BUFSZ;
        mma_chunk<8>(acc, bo + T_AHI, bo + T_ALO, bo + T_BHI, bo + T_BLO, wm, wn, lane);
    }

    const int g  = lane >> 2;
    const int tg = (lane & 3) * 2;
#pragma unroll
    for (int i = 0; i < 2; i++) {
#pragma unroll
        for (int j = 0; j < 8; j++) {
            int row = bm + wm + i * 16 + g;
            int col = bn + wn + j * 8 + tg;
            float b0 = bias[col], b1 = bias[col + 1];
            *(float2*)&Cf[(size_t)row * DIM + col] =
                make_float2(acc[i][j][0] + b0, acc[i][j][1] + b1);
            *(float2*)&Cf[(size_t)(row + 8) * DIM + col] =
                make_float2(acc[i][j][2] + b0, acc[i][j][3] + b1);
        }
    }
}

// ===========================================================================
// QK: scores[bh,s,t] = 0.125 * q_h[s,:].k_h[t,:]  (K=64, bf16 hi/lo inputs)
// Score stores use streaming (.cs) to keep L2 for Q/K tiles.
// ===========================================================================
__global__ __launch_bounds__(256, 2) void wm_gemm_qk(
    const bf16* __restrict__ qhi, const bf16* __restrict__ qlo,
    const bf16* __restrict__ khi, const bf16* __restrict__ klo,
    float* __restrict__ scores)
{
    extern __shared__ char smem[];
    const uint32_t sb = smem_u32(smem);
    const int tid  = threadIdx.x;
    const int wid  = tid >> 5, lane = tid & 31;
    const int bm = blockIdx.y * 128, bn = blockIdx.x * 128;
    const int bh = blockIdx.z;
    const int b = bh >> 4, h = bh & 15;
    const size_t aoff = (size_t)(b * SEQ + bm) * DIM + h * DKH;
    const size_t boff = (size_t)(b * SEQ + bn) * DIM + h * DKH;
    const bf16* Ah = qhi + aoff;
    const bf16* Al = qlo + aoff;
    const bf16* Bh = khi + boff;
    const bf16* Bl = klo + boff;
    float* C = scores + (size_t)bh * SEQ * SEQ;
    const int wm = (wid & 3) * 32;
    const int wn = (wid >> 2) * 64;

    cpa_tile_128(Ah, Al, DIM, sb + T_AHI, sb + T_ALO, tid);
    cpa_tile_128(Bh, Bl, DIM, sb + T_BHI, sb + T_BLO, tid);
    cp_commit();

    float acc[2][8][4] = {};
#pragma unroll
    for (int c = 0; c < 2; c++) {
        cp_wait<0>();
        __syncthreads();
        if (c == 0) {
            uint32_t bo = sb + BUFSZ;
            cpa_tile_128(Ah + 32, Al + 32, DIM, bo + T_AHI, bo + T_ALO, tid);
            cpa_tile_128(Bh + 32, Bl + 32, DIM, bo + T_BHI, bo + T_BLO, tid);
            cp_commit();
        }
        uint32_t bo = sb + (c & 1) * BUFSZ;
        mma_chunk<8>(acc, bo + T_AHI, bo + T_ALO, bo + T_BHI, bo + T_BLO, wm, wn, lane);
    }

    const int g  = lane >> 2;
    const int tg = (lane & 3) * 2;
#pragma unroll
    for (int i = 0; i < 2; i++) {
#pragma unroll
        for (int j = 0; j < 8; j++) {
            int row = bm + wm + i * 16 + g;
            int col = bn + wn + j * 8 + tg;
            __stcs((float2*)&C[(size_t)row * SEQ + col],
                   make_float2(acc[i][j][0] * 0.125f, acc[i][j][1] * 0.125f));
            __stcs((float2*)&C[(size_t)(row + 8) * SEQ + col],
                   make_float2(acc[i][j][2] * 0.125f, acc[i][j][3] * 0.125f));
        }
    }
}

// ===========================================================================
// Row softmax, in place; 2 rows per 512-thread block; streaming ld/st
// ===========================================================================
__global__ __launch_bounds__(512) void softmax2048(float* __restrict__ sc)
{
    const int grp = threadIdx.x >> 8;          // 0 or 1 (row within block)
    const int tid = threadIdx.x & 255;
    float* row = sc + (size_t)(blockIdx.x * 2 + grp) * SEQ;

    float4 v0 = __ldcs((const float4*)(row + tid * 4));
    float4 v1 = __ldcs((const float4*)(row + 1024 + tid * 4));

    float m = fmaxf(fmaxf(fmaxf(v0.x, v0.y), fmaxf(v0.z, v0.w)),
                    fmaxf(fmaxf(v1.x, v1.y), fmaxf(v1.z, v1.w)));
#pragma unroll
    for (int off = 16; off > 0; off >>= 1)
        m = fmaxf(m, __shfl_xor_sync(0xffffffffu, m, off));
    __shared__ float sm[2][8];
    if ((tid & 31) == 0) sm[grp][tid >> 5] = m;
    __syncthreads();
    float bmax = sm[grp][0];
#pragma unroll
    for (int w = 1; w < 8; w++) bmax = fmaxf(bmax, sm[grp][w]);

    v0.x = __expf(v0.x - bmax); v0.y = __expf(v0.y - bmax);
    v0.z = __expf(v0.z - bmax); v0.w = __expf(v0.w - bmax);
    v1.x = __expf(v1.x - bmax); v1.y = __expf(v1.y - bmax);
    v1.z = __expf(v1.z - bmax); v1.w = __expf(v1.w - bmax);

    float s = (v0.x + v0.y + v0.z + v0.w) + (v1.x + v1.y + v1.z + v1.w);
#pragma unroll
    for (int off = 16; off > 0; off >>= 1)
        s += __shfl_xor_sync(0xffffffffu, s, off);
    __shared__ float ss[2][8];
    if ((tid & 31) == 0) ss[grp][tid >> 5] = s;
    __syncthreads();
    float tot = ss[grp][0];
#pragma unroll
    for (int w = 1; w < 8; w++) tot += ss[grp][w];
    float inv = 1.0f / tot;

    v0.x *= inv; v0.y *= inv; v0.z *= inv; v0.w *= inv;
    v1.x *= inv; v1.y *= inv; v1.z *= inv; v1.w *= inv;
    __stcs((float4*)(row + tid * 4), v0);
    __stcs((float4*)(row + 1024 + tid * 4), v1);
}

// ===========================================================================
// PV: blended = P @ V per head; register-prefetch pipeline over fp32 inputs.
// Score loads streaming (.cs). Writes blend as split hi/lo bf16.
// ===========================================================================
__global__ __launch_bounds__(256, 2) void wm_gemm_pv(
    const float* __restrict__ scores, const float* __restrict__ v,
    bf16* __restrict__ blhi, bf16* __restrict__ bllo)
{
    extern __shared__ char smem[];
    const uint32_t sb = smem_u32(smem);
    const int tid  = threadIdx.x;
    const int wid  = tid >> 5, lane = tid & 31;
    const int bm = blockIdx.x * 128;
    const int bh = blockIdx.z;
    const int b = bh >> 4, h = bh & 15;
    const float* A = scores + (size_t)bh * SEQ * SEQ + (size_t)bm * SEQ;
    const float* V = v + (size_t)b * SEQ * DIM + h * DKH;
    const int wm = (wid & 3) * 32;
    const int wn = (wid >> 2) * 32;

    float4 pa[4];
    float4 pv[2];

    const int ar = tid >> 3,  ac4 = (tid & 7) * 4;
    const int vt = tid >> 4,  vd4 = (tid & 15) * 4;

#define PV_PREFETCH(c) do { \
        const float* Ac = A + (c) * 32; \
        const float* Vc = V + (size_t)((c) * 32) * DIM; \
        pa[0] = __ldcs((const float4*)(Ac + (size_t)(ar)      * SEQ + ac4)); \
        pa[1] = __ldcs((const float4*)(Ac + (size_t)(ar + 32) * SEQ + ac4)); \
        pa[2] = __ldcs((const float4*)(Ac + (size_t)(ar + 64) * SEQ + ac4)); \
        pa[3] = __ldcs((const float4*)(Ac + (size_t)(ar + 96) * SEQ + ac4)); \
        pv[0] = *(const float4*)(Vc + (size_t)(vt)      * DIM + vd4); \
        pv[1] = *(const float4*)(Vc + (size_t)(vt + 16) * DIM + vd4); \
    } while (0)

    PV_PREFETCH(0);

    float acc[2][4][4] = {};
    for (int c = 0; c < (SEQ >> 5); c++) {
#pragma unroll
        for (int it = 0; it < 4; it++) {
            uint32_t h01, l01, h23, l23;
            split2(pa[it].x, pa[it].y, h01, l01);
            split2(pa[it].z, pa[it].w, h23, l23);
            uint32_t off = (uint32_t)(ar + it * 32) * STB + ac4 * 2;
            *(uint2*)(smem + T_AHI + off) = make_uint2(h01, h23);
            *(uint2*)(smem + T_ALO + off) = make_uint2(l01, l23);
        }
#pragma unroll
        for (int it = 0; it < 2; it++) {
            int t = vt + it * 16;
            float vv[4] = {pv[it].x, pv[it].y, pv[it].z, pv[it].w};
#pragma unroll
            for (int j = 0; j < 4; j++) {
                bf16 hh = __float2bfloat16_rn(vv[j]);
                bf16 ll = __float2bfloat16_rn(vv[j] - __bfloat162float(hh));
                uint32_t off = (uint32_t)(vd4 + j) * STB + t * 2;
                *(bf16*)(smem + OFF_BHI_PV + off) = hh;
                *(bf16*)(smem + OFF_BLO_PV + off) = ll;
            }
        }
        __syncthreads();
        if (c + 1 < (SEQ >> 5)) PV_PREFETCH(c + 1);
        mma_chunk<4>(acc, sb + T_AHI, sb + T_ALO, sb + OFF_BHI_PV, sb + OFF_BLO_PV,
                     wm, wn, lane);
        __syncthreads();
    }
#undef PV_PREFETCH

    const int g  = lane >> 2;
    const int tg = (lane & 3) * 2;
    const size_t base = (size_t)b * SEQ * DIM + h * DKH;
#pragma unroll
    for (int i = 0; i < 2; i++) {
#pragma unroll
        for (int j = 0; j < 4; j++) {
            int row = bm + wm + i * 16 + g;
            int col = wn + j * 8 + tg;
            uint32_t hh, ll;
            split2(acc[i][j][0], acc[i][j][1], hh, ll);
            *(uint32_t*)&blhi[base + (size_t)row * DIM + col] = hh;
            *(uint32_t*)&bllo[base + (size_t)row * DIM + col] = ll;
            split2(acc[i][j][2], acc[i][j][3], hh, ll);
            *(uint32_t*)&blhi[base + (size_t)(row + 8) * DIM + col] = hh;
            *(uint32_t*)&bllo[base + (size_t)(row + 8) * DIM + col] = ll;
        }
    }
}

// ===========================================================================
extern "C" void kernel_launch(void* const* d_in, const int* in_sizes, int n_in,
                              void* d_out, int out_size)
{
    const float* query = (const float*)d_in[0];
    const float* key   = (const float*)d_in[1];
    const float* value = (const float*)d_in[2];
    const float* Wq = (const float*)d_in[3];
    const float* bq = (const float*)d_in[4];
    const float* Wk = (const float*)d_in[5];
    const float* bk = (const float*)d_in[6];
    const float* Wv = (const float*)d_in[7];
    const float* bv = (const float*)d_in[8];
    const float* Wo = (const float*)d_in[9];
    const float* bo = (const float*)d_in[10];

    float* out    = (float*)d_out;
    float* scores = out + (size_t)BB * SEQ * DIM;

    bf16 *inqh, *inql, *inkh, *inkl, *invh, *invl;
    bf16 *wqh, *wql, *wkh, *wkl, *wvh, *wvl, *woh, *wol;
    bf16 *qh, *ql, *kh, *kl, *blh, *bll;
    float *vp;
    cudaGetSymbolAddress((void**)&inqh, g_inq_hi); cudaGetSymbolAddress((void**)&inql, g_inq_lo);
    cudaGetSymbolAddress((void**)&inkh, g_ink_hi); cudaGetSymbolAddress((void**)&inkl, g_ink_lo);
    cudaGetSymbolAddress((void**)&invh, g_inv_hi); cudaGetSymbolAddress((void**)&invl, g_inv_lo);
    cudaGetSymbolAddress((void**)&wqh, g_wq_hi); cudaGetSymbolAddress((void**)&wql, g_wq_lo);
    cudaGetSymbolAddress((void**)&wkh, g_wk_hi); cudaGetSymbolAddress((void**)&wkl, g_wk_lo);
    cudaGetSymbolAddress((void**)&wvh, g_wv_hi); cudaGetSymbolAddress((void**)&wvl, g_wv_lo);
    cudaGetSymbolAddress((void**)&woh, g_wo_hi); cudaGetSymbolAddress((void**)&wol, g_wo_lo);
    cudaGetSymbolAddress((void**)&qh, g_q_hi);   cudaGetSymbolAddress((void**)&ql, g_q_lo);
    cudaGetSymbolAddress((void**)&kh, g_k_hi);   cudaGetSymbolAddress((void**)&kl, g_k_lo);
    cudaGetSymbolAddress((void**)&blh, g_bl_hi); cudaGetSymbolAddress((void**)&bll, g_bl_lo);
    cudaGetSymbolAddress((void**)&vp, g_v);

    cudaFuncSetAttribute(gemm_qkv,  cudaFuncAttributeMaxDynamicSharedMemorySize, SMEM_G);
    cudaFuncSetAttribute(gemm_wo,   cudaFuncAttributeMaxDynamicSharedMemorySize, SMEM_G);
    cudaFuncSetAttribute(wm_gemm_qk, cudaFuncAttributeMaxDynamicSharedMemorySize, SMEM_G);
    cudaFuncSetAttribute(wm_gemm_pv, cudaFuncAttributeMaxDynamicSharedMemorySize, SMEM_PV);

    // 1) pre-split: one launch for the 3 inputs, one for the 4 weights
    {
        SplitBatch si = {};
        si.src[0] = (const float4*)query; si.hi[0] = (uint2*)inqh; si.lo[0] = (uint2*)inql;
        si.src[1] = (const float4*)key;   si.hi[1] = (uint2*)inkh; si.lo[1] = (uint2*)inkl;
        si.src[2] = (const float4*)value; si.hi[2] = (uint2*)invh; si.lo[2] = (uint2*)invl;
        split_batch<<<dim3(MTOT/4/256, 3), 256>>>(si, MTOT/4);

        SplitBatch sw = {};
        sw.src[0] = (const float4*)Wq; sw.hi[0] = (uint2*)wqh; sw.lo[0] = (uint2*)wql;
        sw.src[1] = (const float4*)Wk; sw.hi[1] = (uint2*)wkh; sw.lo[1] = (uint2*)wkl;
        sw.src[2] = (const float4*)Wv; sw.hi[2] = (uint2*)wvh; sw.lo[2] = (uint2*)wvl;
        sw.src[3] = (const float4*)Wo; sw.hi[3] = (uint2*)woh; sw.lo[3] = (uint2*)wol;
        split_batch<<<dim3(DIM*DIM/4/256, 4), 256>>>(sw, DIM*DIM/4);
    }

    // 2) merged QKV projections (one launch, grid.z = 3)
    {
        ProjArgs pa = {};
        pa.Ah[0] = inqh; pa.Al[0] = inql; pa.Bh[0] = wqh; pa.Bl[0] = wql;
        pa.Ah[1] = inkh; pa.Al[1] = inkl; pa.Bh[1] = wkh; pa.Bl[1] = wkl;
        pa.Ah[2] = invh; pa.Al[2] = invl; pa.Bh[2] = wvh; pa.Bl[2] = wvl;
        pa.bias[0] = bq; pa.bias[1] = bk; pa.bias[2] = bv;
        pa.Chi[0] = qh; pa.Clo[0] = ql;
        pa.Chi[1] = kh; pa.Clo[1] = kl;
        pa.Cf = vp;
        gemm_qkv<<<dim3(DIM / 128, (BB * SEQ) / 128, 3), 256, SMEM_G>>>(pa);
    }

    // 3) attention
    wm_gemm_qk<<<dim3(SEQ / 128, SEQ / 128, NBH), 256, SMEM_G>>>(qh, ql, kh, kl, scores);
    softmax2048<<<NBH * SEQ / 2, 512>>>(scores);
    wm_gemm_pv<<<dim3(SEQ / 128, 1, NBH), 256, SMEM_PV>>>(scores, vp, blh, bll);

    // 4) output projection
    gemm_wo<<<dim3(DIM / 128, (BB * SEQ) / 128), 256, SMEM_G>>>(blh, bll, woh, wol, bo, out);
}

// round 11
// speedup vs baseline: 1.1113x; 1.1113x over previous
#include <cuda_runtime.h>
#include <cuda_bf16.h>
#include <cstdint>

#define BB    2
#define SEQ   2048
#define DIM   1024
#define HEADS 16
#define DKH   64
#define MTOT  (BB * SEQ * DIM)      // 4M elements
#define NBH   (BB * HEADS)

typedef __nv_bfloat16 bf16;

// Scratch (allocation-free rule: __device__ globals), 16B-aligned for vector IO
__device__ __align__(16) bf16 g_inq_hi[MTOT], g_inq_lo[MTOT];
__device__ __align__(16) bf16 g_ink_hi[MTOT], g_ink_lo[MTOT];
__device__ __align__(16) bf16 g_inv_hi[MTOT], g_inv_lo[MTOT];
__device__ __align__(16) bf16 g_wq_hi[DIM*DIM], g_wq_lo[DIM*DIM];
__device__ __align__(16) bf16 g_wk_hi[DIM*DIM], g_wk_lo[DIM*DIM];
__device__ __align__(16) bf16 g_wv_hi[DIM*DIM], g_wv_lo[DIM*DIM];
__device__ __align__(16) bf16 g_wo_hi[DIM*DIM], g_wo_lo[DIM*DIM];
__device__ __align__(16) bf16 g_q_hi[MTOT],  g_q_lo[MTOT];
__device__ __align__(16) bf16 g_k_hi[MTOT],  g_k_lo[MTOT];
__device__ __align__(16) bf16 g_bl_hi[MTOT], g_bl_lo[MTOT];
__device__ __align__(16) float g_v[MTOT];
__device__ float2 g_tstats[NBH * 16 * SEQ];   // per (bh, col-tile, row): (max, sumexp)
__device__ float2 g_rowstats[NBH * SEQ];      // per (bh, row): (max, 1/sum)

// ===========================================================================
// PTX primitives (sm_80-era — assembles under compute_103)
// ===========================================================================
__device__ __forceinline__ uint32_t smem_u32(const void* p) {
    uint32_t a;
    asm("{ .reg .u64 t; cvta.to.shared.u64 t, %1; cvt.u32.u64 %0, t; }"
        : "=r"(a) : "l"(p));
    return a;
}

__device__ __forceinline__ void mma16816(float* c, const uint32_t* a, const uint32_t* b) {
    asm volatile("mma.sync.aligned.m16n8k16.row.col.f32.bf16.bf16.f32 "
        "{%0,%1,%2,%3}, {%4,%5,%6,%7}, {%8,%9}, {%0,%1,%2,%3};"
        : "+f"(c[0]), "+f"(c[1]), "+f"(c[2]), "+f"(c[3])
        : "r"(a[0]), "r"(a[1]), "r"(a[2]), "r"(a[3]), "r"(b[0]), "r"(b[1]));
}

#define STB  80   // bytes per smem tile row (64B data + 16B pad)

__device__ __forceinline__ void ldsmA4(uint32_t* r, uint32_t base, int m0, int k0, int lane) {
    uint32_t addr = base + (uint32_t)(m0 + (lane & 15)) * STB
                         + (uint32_t)(k0 + (lane >> 4) * 8) * 2;
    asm volatile("ldmatrix.sync.aligned.m8n8.x4.shared.b16 {%0,%1,%2,%3}, [%4];"
        : "=r"(r[0]), "=r"(r[1]), "=r"(r[2]), "=r"(r[3]) : "r"(addr));
}

__device__ __forceinline__ void ldsmB2(uint32_t* r, uint32_t base, int n0, int k0, int lane) {
    uint32_t addr = base + (uint32_t)(n0 + (lane & 7)) * STB
                         + (uint32_t)(k0 + ((lane >> 3) & 1) * 8) * 2;
    asm volatile("ldmatrix.sync.aligned.m8n8.x2.shared.b16 {%0,%1}, [%2];"
        : "=r"(r[0]), "=r"(r[1]) : "r"(addr));
}

__device__ __forceinline__ void cp16(uint32_t dst, const void* src) {
    asm volatile("cp.async.ca.shared.global [%0], [%1], 16;"
        :: "r"(dst), "l"(src) : "memory");
}
__device__ __forceinline__ void cp_commit() {
    asm volatile("cp.async.commit_group;" ::: "memory");
}
template<int N> __device__ __forceinline__ void cp_wait() {
    asm volatile("cp.async.wait_group %0;" :: "n"(N) : "memory");
}

// ===========================================================================
// split-bf16 helpers
// ===========================================================================
__device__ __forceinline__ uint32_t pack2(bf16 a, bf16 b) {
    return (uint32_t)__bfloat16_as_ushort(a) | ((uint32_t)__bfloat16_as_ushort(b) << 16);
}
__device__ __forceinline__ void split2(float a, float b, uint32_t& hi, uint32_t& lo) {
    bf16 ha = __float2bfloat16_rn(a);
    bf16 hb = __float2bfloat16_rn(b);
    bf16 la = __float2bfloat16_rn(a - __bfloat162float(ha));
    bf16 lb = __float2bfloat16_rn(b - __bfloat162float(hb));
    hi = pack2(ha, hb);
    lo = pack2(la, lb);
}

// Batched elementwise fp32 -> (hi, lo) bf16 (grid.y selects tensor)
struct SplitBatch {
    const float4* src[4];
    uint2* hi[4];
    uint2* lo[4];
};

__global__ __launch_bounds__(256) void split_batch(SplitBatch args, int n4)
{
    const int z = blockIdx.y;
    int i = blockIdx.x * 256 + threadIdx.x;
    if (i < n4) {
        float4 v = args.src[z][i];
        uint32_t h01, l01, h23, l23;
        split2(v.x, v.y, h01, l01);
        split2(v.z, v.w, h23, l23);
        args.hi[z][i] = make_uint2(h01, h23);
        args.lo[z][i] = make_uint2(l01, l23);
    }
}

// ===========================================================================
// cp.async tile loaders: one K=32 chunk (64B/row), 128 rows, hi+lo
// ===========================================================================
__device__ __forceinline__ void cpa_tile_128(
    const bf16* __restrict__ hi, const bf16* __restrict__ lo, int ld,
    uint32_t smem_hi, uint32_t smem_lo, int tid)
{
#pragma unroll
    for (int it = 0; it < 2; it++) {
        int idx = tid + it * 256;        // 0..511
        int r = idx >> 2, j = idx & 3;
        size_t go = (size_t)r * ld + j * 8;
        uint32_t so = (uint32_t)r * STB + j * 16;
        cp16(smem_hi + so, hi + go);
        cp16(smem_lo + so, lo + go);
    }
}

// Smem offsets within one pipeline buffer (tile = 128 x STB = 10240 B)
#define T_AHI 0u
#define T_ALO 10240u
#define T_BHI 20480u
#define T_BLO 30720u
#define BUFSZ 40960u
#define SMEM_G (2 * 40960)           // double-buffered
#define OFF_BHI_PV 20480u
#define OFF_BLO_PV 25600u
#define SMEM_PV (30720 + 1024)       // + 128 x float2 rowstats

// ===========================================================================
// 3-term MMA over one 32-K chunk (shared fragments, long RAW distance)
// ===========================================================================
template<int NJ>
__device__ __forceinline__ void mma_chunk(
    float (*acc)[NJ][4], uint32_t aHi, uint32_t aLo, uint32_t bHi, uint32_t bLo,
    int wm, int wn, int lane)
{
#pragma unroll
    for (int k0 = 0; k0 < 32; k0 += 16) {
        uint32_t ah0[4], ah1[4], al0[4], al1[4];
        ldsmA4(ah0, aHi, wm,      k0, lane);
        ldsmA4(ah1, aHi, wm + 16, k0, lane);
        ldsmA4(al0, aLo, wm,      k0, lane);
        ldsmA4(al1, aLo, wm + 16, k0, lane);
        uint32_t bf[NJ][2];
#pragma unroll
        for (int j = 0; j < NJ; j++) ldsmB2(bf[j], bHi, wn + j * 8, k0, lane);
#pragma unroll
        for (int j = 0; j < NJ; j++) {
            mma16816(acc[0][j], ah0, bf[j]);
            mma16816(acc[1][j], ah1, bf[j]);
        }
#pragma unroll
        for (int j = 0; j < NJ; j++) {
            mma16816(acc[0][j], al0, bf[j]);
            mma16816(acc[1][j], al1, bf[j]);
        }
#pragma unroll
        for (int j = 0; j < NJ; j++) ldsmB2(bf[j], bLo, wn + j * 8, k0, lane);
#pragma unroll
        for (int j = 0; j < NJ; j++) {
            mma16816(acc[0][j], ah0, bf[j]);
            mma16816(acc[1][j], ah1, bf[j]);
        }
    }
}

// ===========================================================================
// Generic bf16 GEMM: C[M,N] = A[M,K] @ B[N,K]^T + bias
// A,B pre-split hi/lo bf16. OUT_SPLIT: write hi/lo bf16, else fp32.
// ===========================================================================
template<bool OUT_SPLIT>
__global__ __launch_bounds__(256, 2) void gemm_bf16(
    const bf16* __restrict__ Ahi, const bf16* __restrict__ Alo, int lda,
    const bf16* __restrict__ Bhi, const bf16* __restrict__ Blo, int ldb,
    const float* __restrict__ bias, int K, int N,
    float* __restrict__ Cf, bf16* __restrict__ Chi, bf16* __restrict__ Clo)
{
    extern __shared__ char smem[];
    const uint32_t sb = smem_u32(smem);
    const int tid  = threadIdx.x;
    const int wid  = tid >> 5, lane = tid & 31;
    const int bm = blockIdx.y * 128, bn = blockIdx.x * 128;
    const int wm = (wid & 3) * 32;
    const int wn = (wid >> 2) * 64;

    const bf16* Ah = Ahi + (size_t)bm * lda;
    const bf16* Al = Alo + (size_t)bm * lda;
    const bf16* Bh = Bhi + (size_t)bn * ldb;
    const bf16* Bl = Blo + (size_t)bn * ldb;
    const int nc = K >> 5;

    cpa_tile_128(Ah, Al, lda, sb + T_AHI, sb + T_ALO, tid);
    cpa_tile_128(Bh, Bl, ldb, sb + T_BHI, sb + T_BLO, tid);
    cp_commit();

    float acc[2][8][4] = {};
    for (int c = 0; c < nc; c++) {
        cp_wait<0>();
        __syncthreads();
        if (c + 1 < nc) {
            uint32_t bo = sb + ((c + 1) & 1) * BUFSZ;
            cpa_tile_128(Ah + (c+1)*32, Al + (c+1)*32, lda, bo + T_AHI, bo + T_ALO, tid);
            cpa_tile_128(Bh + (c+1)*32, Bl + (c+1)*32, ldb, bo + T_BHI, bo + T_BLO, tid);
            cp_commit();
        }
        uint32_t bo = sb + (c & 1) * BUFSZ;
        mma_chunk<8>(acc, bo + T_AHI, bo + T_ALO, bo + T_BHI, bo + T_BLO, wm, wn, lane);
    }

    const int g  = lane >> 2;
    const int tg = (lane & 3) * 2;
#pragma unroll
    for (int i = 0; i < 2; i++) {
#pragma unroll
        for (int j = 0; j < 8; j++) {
            int row = bm + wm + i * 16 + g;
            int col = bn + wn + j * 8 + tg;
            float b0 = bias[col], b1 = bias[col + 1];
            float x0 = acc[i][j][0] + b0, x1 = acc[i][j][1] + b1;
            float x2 = acc[i][j][2] + b0, x3 = acc[i][j][3] + b1;
            if (OUT_SPLIT) {
                uint32_t h, l;
                split2(x0, x1, h, l);
                *(uint32_t*)&Chi[(size_t)row * N + col] = h;
                *(uint32_t*)&Clo[(size_t)row * N + col] = l;
                split2(x2, x3, h, l);
                *(uint32_t*)&Chi[(size_t)(row + 8) * N + col] = h;
                *(uint32_t*)&Clo[(size_t)(row + 8) * N + col] = l;
            } else {
                *(float2*)&Cf[(size_t)row * N + col] = make_float2(x0, x1);
                *(float2*)&Cf[(size_t)(row + 8) * N + col] = make_float2(x2, x3);
            }
        }
    }
}

// ===========================================================================
// QK: raw scaled scores (stcs) + per-tile softmax stats (reuses dead smem)
// ===========================================================================
__global__ __launch_bounds__(256, 2) void wm_gemm_qk(
    const bf16* __restrict__ qhi, const bf16* __restrict__ qlo,
    const bf16* __restrict__ khi, const bf16* __restrict__ klo,
    float* __restrict__ scores, float2* __restrict__ tstats)
{
    extern __shared__ char smem[];
    const uint32_t sb = smem_u32(smem);
    const int tid  = threadIdx.x;
    const int wid  = tid >> 5, lane = tid & 31;
    const int bm = blockIdx.y * 128, bn = blockIdx.x * 128;
    const int bh = blockIdx.z;
    const int b = bh >> 4, h = bh & 15;
    const size_t aoff = (size_t)(b * SEQ + bm) * DIM + h * DKH;
    const size_t boff = (size_t)(b * SEQ + bn) * DIM + h * DKH;
    const bf16* Ah = qhi + aoff;
    const bf16* Al = qlo + aoff;
    const bf16* Bh = khi + boff;
    const bf16* Bl = klo + boff;
    float* C = scores + (size_t)bh * SEQ * SEQ;
    const int wm = (wid & 3) * 32;
    const int wn = (wid >> 2) * 64;

    cpa_tile_128(Ah, Al, DIM, sb + T_AHI, sb + T_ALO, tid);
    cpa_tile_128(Bh, Bl, DIM, sb + T_BHI, sb + T_BLO, tid);
    cp_commit();

    float acc[2][8][4] = {};
#pragma unroll
    for (int c = 0; c < 2; c++) {
        cp_wait<0>();
        __syncthreads();
        if (c == 0) {
            uint32_t bo = sb + BUFSZ;
            cpa_tile_128(Ah + 32, Al + 32, DIM, bo + T_AHI, bo + T_ALO, tid);
            cpa_tile_128(Bh + 32, Bl + 32, DIM, bo + T_BHI, bo + T_BLO, tid);
            cp_commit();
        }
        uint32_t bo = sb + (c & 1) * BUFSZ;
        mma_chunk<8>(acc, bo + T_AHI, bo + T_ALO, bo + T_BHI, bo + T_BLO, wm, wn, lane);
    }

    // scale accumulators, store raw scaled scores (streaming)
#pragma unroll
    for (int i = 0; i < 2; i++)
#pragma unroll
        for (int j = 0; j < 8; j++)
#pragma unroll
            for (int e = 0; e < 4; e++) acc[i][j][e] *= 0.125f;

    const int g  = lane >> 2;
    const int tg = (lane & 3) * 2;
#pragma unroll
    for (int i = 0; i < 2; i++) {
#pragma unroll
        for (int j = 0; j < 8; j++) {
            int row = bm + wm + i * 16 + g;
            int col = bn + wn + j * 8 + tg;
            __stcs((float2*)&C[(size_t)row * SEQ + col],
                   make_float2(acc[i][j][0], acc[i][j][1]));
            __stcs((float2*)&C[(size_t)(row + 8) * SEQ + col],
                   make_float2(acc[i][j][2], acc[i][j][3]));
        }
    }

    // per-tile row stats: (max, sumexp) over this CTA's 128 columns.
    // Reuse pipeline buffer 0 (mainloop finished with buffer 1).
    float2* st = (float2*)smem;                // [128 rows][2 col-halves]
    const int half = wid >> 2;
#pragma unroll
    for (int i = 0; i < 2; i++) {
#pragma unroll
        for (int p = 0; p < 2; p++) {
            float m = -3.0e38f;
#pragma unroll
            for (int j = 0; j < 8; j++)
                m = fmaxf(m, fmaxf(acc[i][j][2 * p], acc[i][j][2 * p + 1]));
            m = fmaxf(m, __shfl_xor_sync(0xffffffffu, m, 1));
            m = fmaxf(m, __shfl_xor_sync(0xffffffffu, m, 2));
            float s = 0.f;
#pragma unroll
            for (int j = 0; j < 8; j++)
                s += __expf(acc[i][j][2 * p] - m) + __expf(acc[i][j][2 * p + 1] - m);
            s += __shfl_xor_sync(0xffffffffu, s, 1);
            s += __shfl_xor_sync(0xffffffffu, s, 2);
            if ((lane & 3) == 0)
                st[(wm + i * 16 + p * 8 + g) * 2 + half] = make_float2(m, s);
        }
    }
    __syncthreads();
    if (tid < 128) {
        float2 a = st[tid * 2 + 0], bsv = st[tid * 2 + 1];
        float M = fmaxf(a.x, bsv.x);
        float S = a.y * __expf(a.x - M) + bsv.y * __expf(bsv.x - M);
        tstats[((size_t)bh * 16 + blockIdx.x) * SEQ + bm + tid] = make_float2(M, S);
    }
}

// ===========================================================================
// Reduce 16 per-tile stats -> per-row (max, 1/sum)
// ===========================================================================
__global__ __launch_bounds__(256) void stats_reduce(
    const float2* __restrict__ tstats, float2* __restrict__ rowstats)
{
    const int row = blockIdx.x * 256 + threadIdx.x;
    const int bh  = blockIdx.y;
    float M = -3.0e38f;
    float2 t[16];
#pragma unroll
    for (int i = 0; i < 16; i++) {
        t[i] = tstats[((size_t)bh * 16 + i) * SEQ + row];
        M = fmaxf(M, t[i].x);
    }
    float S = 0.f;
#pragma unroll
    for (int i = 0; i < 16; i++) S += t[i].y * __expf(t[i].x - M);
    rowstats[(size_t)bh * SEQ + row] = make_float2(M, 1.0f / S);
}

// ===========================================================================
// Fused softmax + PV: reads raw scores (streaming), computes P, writes P
// (required output, stcs), feeds P into split-bf16 MMA. Blend out as hi/lo.
// ===========================================================================
__global__ __launch_bounds__(256, 2) void wm_gemm_pv(
    float* __restrict__ scores, const float* __restrict__ v,
    const float2* __restrict__ rowstats,
    bf16* __restrict__ blhi, bf16* __restrict__ bllo)
{
    extern __shared__ char smem[];
    const uint32_t sb = smem_u32(smem);
    const int tid  = threadIdx.x;
    const int wid  = tid >> 5, lane = tid & 31;
    const int bm = blockIdx.x * 128;
    const int bh = blockIdx.z;
    const int b = bh >> 4, h = bh & 15;
    float* A = scores + (size_t)bh * SEQ * SEQ + (size_t)bm * SEQ;
    const float* V = v + (size_t)b * SEQ * DIM + h * DKH;
    const int wm = (wid & 3) * 32;
    const int wn = (wid >> 2) * 32;

    float2* rs = (float2*)(smem + 30720);
    if (tid < 128) rs[tid] = rowstats[(size_t)bh * SEQ + bm + tid];
    __syncthreads();

    float4 pa[4];
    float4 pv[2];

    const int ar = tid >> 3,  ac4 = (tid & 7) * 4;
    const int vt = tid >> 4,  vd4 = (tid & 15) * 4;

#define PV_PREFETCH(c) do { \
        const float* Ac = A + (c) * 32; \
        const float* Vc = V + (size_t)((c) * 32) * DIM; \
        pa[0] = __ldcs((const float4*)(Ac + (size_t)(ar)      * SEQ + ac4)); \
        pa[1] = __ldcs((const float4*)(Ac + (size_t)(ar + 32) * SEQ + ac4)); \
        pa[2] = __ldcs((const float4*)(Ac + (size_t)(ar + 64) * SEQ + ac4)); \
        pa[3] = __ldcs((const float4*)(Ac + (size_t)(ar + 96) * SEQ + ac4)); \
        pv[0] = *(const float4*)(Vc + (size_t)(vt)      * DIM + vd4); \
        pv[1] = *(const float4*)(Vc + (size_t)(vt + 16) * DIM + vd4); \
    } while (0)

    PV_PREFETCH(0);

    float acc[2][4][4] = {};
    for (int c = 0; c < (SEQ >> 5); c++) {
        // store phase: softmax in registers, write P, stage bf16 hi/lo
#pragma unroll
        for (int it = 0; it < 4; it++) {
            int r = ar + it * 32;
            float2 st = rs[r];
            float4 p;
            p.x = __expf(pa[it].x - st.x) * st.y;
            p.y = __expf(pa[it].y - st.x) * st.y;
            p.z = __expf(pa[it].z - st.x) * st.y;
            p.w = __expf(pa[it].w - st.x) * st.y;
            __stcs((float4*)(A + (size_t)c * 32 + (size_t)r * SEQ + ac4), p);
            uint32_t h01, l01, h23, l23;
            split2(p.x, p.y, h01, l01);
            split2(p.z, p.w, h23, l23);
            uint32_t off = (uint32_t)r * STB + ac4 * 2;
            *(uint2*)(smem + T_AHI + off) = make_uint2(h01, h23);
            *(uint2*)(smem + T_ALO + off) = make_uint2(l01, l23);
        }
#pragma unroll
        for (int it = 0; it < 2; it++) {
            int t = vt + it * 16;
            float vv[4] = {pv[it].x, pv[it].y, pv[it].z, pv[it].w};
#pragma unroll
            for (int j = 0; j < 4; j++) {
                bf16 hh = __float2bfloat16_rn(vv[j]);
                bf16 ll = __float2bfloat16_rn(vv[j] - __bfloat162float(hh));
                uint32_t off = (uint32_t)(vd4 + j) * STB + t * 2;
                *(bf16*)(smem + OFF_BHI_PV + off) = hh;
                *(bf16*)(smem + OFF_BLO_PV + off) = ll;
            }
        }
        __syncthreads();
        if (c + 1 < (SEQ >> 5)) PV_PREFETCH(c + 1);   // LDGs overlap MMAs
        mma_chunk<4>(acc, sb + T_AHI, sb + T_ALO, sb + OFF_BHI_PV, sb + OFF_BLO_PV,
                     wm, wn, lane);
        __syncthreads();
    }
#undef PV_PREFETCH

    const int g  = lane >> 2;
    const int tg = (lane & 3) * 2;
    const size_t base = (size_t)b * SEQ * DIM + h * DKH;
#pragma unroll
    for (int i = 0; i < 2; i++) {
#pragma unroll
        for (int j = 0; j < 4; j++) {
            int row = bm + wm + i * 16 + g;
            int col = wn + j * 8 + tg;
            uint32_t hh, ll;
            split2(acc[i][j][0], acc[i][j][1], hh, ll);
            *(uint32_t*)&blhi[base + (size_t)row * DIM + col] = hh;
            *(uint32_t*)&bllo[base + (size_t)row * DIM + col] = ll;
            split2(acc[i][j][2], acc[i][j][3], hh, ll);
            *(uint32_t*)&blhi[base + (size_t)(row + 8) * DIM + col] = hh;
            *(uint32_t*)&bllo[base + (size_t)(row + 8) * DIM + col] = ll;
        }
    }
}

// ===========================================================================
extern "C" void kernel_launch(void* const* d_in, const int* in_sizes, int n_in,
                              void* d_out, int out_size)
{
    const float* query = (const float*)d_in[0];
    const float* key   = (const float*)d_in[1];
    const float* value = (const float*)d_in[2];
    const float* Wq = (const float*)d_in[3];
    const float* bq = (const float*)d_in[4];
    const float* Wk = (const float*)d_in[5];
    const float* bk = (const float*)d_in[6];
    const float* Wv = (const float*)d_in[7];
    const float* bv = (const float*)d_in[8];
    const float* Wo = (const float*)d_in[9];
    const float* bo = (const float*)d_in[10];

    float* out    = (float*)d_out;
    float* scores = out + (size_t)BB * SEQ * DIM;

    bf16 *inqh, *inql, *inkh, *inkl, *invh, *invl;
    bf16 *wqh, *wql, *wkh, *wkl, *wvh, *wvl, *woh, *wol;
    bf16 *qh, *ql, *kh, *kl, *blh, *bll;
    float *vp;
    float2 *ts, *rsg;
    cudaGetSymbolAddress((void**)&inqh, g_inq_hi); cudaGetSymbolAddress((void**)&inql, g_inq_lo);
    cudaGetSymbolAddress((void**)&inkh, g_ink_hi); cudaGetSymbolAddress((void**)&inkl, g_ink_lo);
    cudaGetSymbolAddress((void**)&invh, g_inv_hi); cudaGetSymbolAddress((void**)&invl, g_inv_lo);
    cudaGetSymbolAddress((void**)&wqh, g_wq_hi); cudaGetSymbolAddress((void**)&wql, g_wq_lo);
    cudaGetSymbolAddress((void**)&wkh, g_wk_hi); cudaGetSymbolAddress((void**)&wkl, g_wk_lo);
    cudaGetSymbolAddress((void**)&wvh, g_wv_hi); cudaGetSymbolAddress((void**)&wvl, g_wv_lo);
    cudaGetSymbolAddress((void**)&woh, g_wo_hi); cudaGetSymbolAddress((void**)&wol, g_wo_lo);
    cudaGetSymbolAddress((void**)&qh, g_q_hi);   cudaGetSymbolAddress((void**)&ql, g_q_lo);
    cudaGetSymbolAddress((void**)&kh, g_k_hi);   cudaGetSymbolAddress((void**)&kl, g_k_lo);
    cudaGetSymbolAddress((void**)&blh, g_bl_hi); cudaGetSymbolAddress((void**)&bll, g_bl_lo);
    cudaGetSymbolAddress((void**)&vp, g_v);
    cudaGetSymbolAddress((void**)&ts, g_tstats);
    cudaGetSymbolAddress((void**)&rsg, g_rowstats);

    cudaFuncSetAttribute(gemm_bf16<true>,  cudaFuncAttributeMaxDynamicSharedMemorySize, SMEM_G);
    cudaFuncSetAttribute(gemm_bf16<false>, cudaFuncAttributeMaxDynamicSharedMemorySize, SMEM_G);
    cudaFuncSetAttribute(wm_gemm_qk,       cudaFuncAttributeMaxDynamicSharedMemorySize, SMEM_G);
    cudaFuncSetAttribute(wm_gemm_pv,       cudaFuncAttributeMaxDynamicSharedMemorySize, SMEM_PV);

    // 1) pre-split inputs + weights (2 batched launches)
    {
        SplitBatch si = {};
        si.src[0] = (const float4*)query; si.hi[0] = (uint2*)inqh; si.lo[0] = (uint2*)inql;
        si.src[1] = (const float4*)key;   si.hi[1] = (uint2*)inkh; si.lo[1] = (uint2*)inkl;
        si.src[2] = (const float4*)value; si.hi[2] = (uint2*)invh; si.lo[2] = (uint2*)invl;
        split_batch<<<dim3(MTOT/4/256, 3), 256>>>(si, MTOT/4);

        SplitBatch sw = {};
        sw.src[0] = (const float4*)Wq; sw.hi[0] = (uint2*)wqh; sw.lo[0] = (uint2*)wql;
        sw.src[1] = (const float4*)Wk; sw.hi[1] = (uint2*)wkh; sw.lo[1] = (uint2*)wkl;
        sw.src[2] = (const float4*)Wv; sw.hi[2] = (uint2*)wvh; sw.lo[2] = (uint2*)wvl;
        sw.src[3] = (const float4*)Wo; sw.hi[3] = (uint2*)woh; sw.lo[3] = (uint2*)wol;
        split_batch<<<dim3(DIM*DIM/4/256, 4), 256>>>(sw, DIM*DIM/4);
    }

    // 2) projections (separate launches — measured faster than merged)
    dim3 gproj(DIM / 128, (BB * SEQ) / 128);
    gemm_bf16<true><<<gproj, 256, SMEM_G>>>(inqh, inql, DIM, wqh, wql, DIM, bq, DIM, DIM,
                                            nullptr, qh, ql);
    gemm_bf16<true><<<gproj, 256, SMEM_G>>>(inkh, inkl, DIM, wkh, wkl, DIM, bk, DIM, DIM,
                                            nullptr, kh, kl);
    gemm_bf16<false><<<gproj, 256, SMEM_G>>>(invh, invl, DIM, wvh, wvl, DIM, bv, DIM, DIM,
                                             vp, nullptr, nullptr);

    // 3) attention: qk (+stats) -> reduce -> fused softmax+PV
    wm_gemm_qk<<<dim3(SEQ / 128, SEQ / 128, NBH), 256, SMEM_G>>>(qh, ql, kh, kl, scores, ts);
    stats_reduce<<<dim3(SEQ / 256, NBH), 256>>>(ts, rsg);
    wm_gemm_pv<<<dim3(SEQ / 128, 1, NBH), 256, SMEM_PV>>>(scores, vp, rsg, blh, bll);

    // 4) output projection
    gemm_bf16<false><<<gproj, 256, SMEM_G>>>(blh, bll, DIM, woh, wol, DIM, bo, DIM, DIM,
                                             out, nullptr, nullptr);
}